// round 5
// baseline (speedup 1.0000x reference)
#include <cuda_runtime.h>
#include <cstdint>

#define HW 36864
#define Cc 256
#define QKV_STRIDE 18874368   // 1152*16*64*16
#define ATTN_ELEMS 75497472   // 1152*16*64*64
#define AVG_ELEMS  73728      // 1152*64

__device__ __align__(16) float g_scratch[2 * QKV_STRIDE];   // q then k: [qkv][win][head][n][d]

__device__ __forceinline__ float tf32r(float x) {
    uint32_t u;
    asm("cvt.rna.tf32.f32 %0, %1;" : "=r"(u) : "f"(x));
    return __uint_as_float(u);
}

__device__ __forceinline__ void mma_tf32(float c[4], const uint32_t a[4], const uint32_t b[2]) {
    asm volatile(
        "mma.sync.aligned.m16n8k8.row.col.f32.tf32.tf32.f32 "
        "{%0,%1,%2,%3}, {%4,%5,%6,%7}, {%8,%9}, {%0,%1,%2,%3};"
        : "+f"(c[0]), "+f"(c[1]), "+f"(c[2]), "+f"(c[3])
        : "r"(a[0]), "r"(a[1]), "r"(a[2]), "r"(a[3]), "r"(b[0]), "r"(b[1]));
}

// ---------------- fused 1x1conv(GEMM, tf32 tensor, pipelined) + BN + ReLU + rearrange --
// C[o,p] = sum_c W[o,c] * X[b,c,p]   M=512(o) N=73728(p) K=256
// Block 128x128, 8 warps (2x4), warp 64x32 = 4x4 m16n8k8 frags.
// K-chunk 16, 2-stage register->smem double buffer, ONE barrier per chunk.
__global__ __launch_bounds__(256) void proj_kernel(
    const float* __restrict__ x, const float* __restrict__ w,
    const float* __restrict__ gamma, const float* __restrict__ beta,
    const float* __restrict__ rmean, const float* __restrict__ rvar)
{
    __shared__ __align__(16) float As[2][128][20];    // [buf][o][k], pad 20 (conflict-free)
    __shared__ __align__(16) float Bs[2][16][136];    // [buf][k][p], pad 136 (conflict-free)
    __shared__ float sinv[128], sbz[128];

    const int tid  = threadIdx.x;
    const int warp = tid >> 5;
    const int lane = tid & 31;
    const int o0   = blockIdx.x * 128;
    const int pg0  = blockIdx.y * 128;
    const int b    = pg0 / HW;
    const int pp0  = pg0 - b * HW;
    const float* xb = x + (size_t)b * (Cc * HW);

    if (tid < 128) {
        int og = o0 + tid;
        float iv = gamma[og] * rsqrtf(rvar[og] + 1e-5f);
        sinv[tid] = iv;
        sbz[tid]  = beta[og] - rmean[og] * iv;
    }

    // per-thread staging addresses
    const int aO  = tid >> 2, aC = (tid & 3) * 4;           // A: 512 float4 / chunk, 2/thread
    const int bR  = tid >> 5, bC = (tid & 31) * 4;          // B: 512 float4 / chunk, 2/thread
    const float* wA0 = &w[(o0 + aO) * Cc + aC];             // + c0
    const float* wA1 = &w[(o0 + aO + 64) * Cc + aC];
    const float* xB0 = &xb[bR * HW + pp0 + bC];             // + c0*HW
    const float* xB1 = &xb[(bR + 8) * HW + pp0 + bC];

    float4 ra0, ra1, rb0, rb1;
    ra0 = *reinterpret_cast<const float4*>(wA0);
    ra1 = *reinterpret_cast<const float4*>(wA1);
    rb0 = *reinterpret_cast<const float4*>(xB0);
    rb1 = *reinterpret_cast<const float4*>(xB1);

    #define STS_STAGE(bf) do {                                                        \
        float4 t0 = ra0, t1 = ra1, t2 = rb0, t3 = rb1;                                \
        t0.x=tf32r(t0.x); t0.y=tf32r(t0.y); t0.z=tf32r(t0.z); t0.w=tf32r(t0.w);       \
        t1.x=tf32r(t1.x); t1.y=tf32r(t1.y); t1.z=tf32r(t1.z); t1.w=tf32r(t1.w);       \
        t2.x=tf32r(t2.x); t2.y=tf32r(t2.y); t2.z=tf32r(t2.z); t2.w=tf32r(t2.w);       \
        t3.x=tf32r(t3.x); t3.y=tf32r(t3.y); t3.z=tf32r(t3.z); t3.w=tf32r(t3.w);       \
        *reinterpret_cast<float4*>(&As[bf][aO][aC])      = t0;                        \
        *reinterpret_cast<float4*>(&As[bf][aO + 64][aC]) = t1;                        \
        *reinterpret_cast<float4*>(&Bs[bf][bR][bC])      = t2;                        \
        *reinterpret_cast<float4*>(&Bs[bf][bR + 8][bC])  = t3;                        \
    } while (0)

    STS_STAGE(0);

    const int wm = (warp >> 2) * 64;
    const int wn = (warp & 3) * 32;

    float acc[4][4][4];
#pragma unroll
    for (int mi = 0; mi < 4; mi++)
#pragma unroll
        for (int ni = 0; ni < 4; ni++)
#pragma unroll
            for (int r = 0; r < 4; r++) acc[mi][ni][r] = 0.f;

#pragma unroll 1
    for (int c = 0; c < 16; c++) {
        if (c < 15) {
            int c1 = (c + 1) * 16;
            ra0 = *reinterpret_cast<const float4*>(wA0 + c1);
            ra1 = *reinterpret_cast<const float4*>(wA1 + c1);
            rb0 = *reinterpret_cast<const float4*>(xB0 + (size_t)c1 * HW);
            rb1 = *reinterpret_cast<const float4*>(xB1 + (size_t)c1 * HW);
        }
        __syncthreads();
        const int bf = c & 1;
#pragma unroll
        for (int kk = 0; kk < 2; kk++) {
            const int kq = kk * 8 + (lane & 3);
            uint32_t a[4][4], bfr[4][2];
#pragma unroll
            for (int mi = 0; mi < 4; mi++) {
                int m = wm + mi * 16 + (lane >> 2);
                a[mi][0] = __float_as_uint(As[bf][m][kq]);
                a[mi][1] = __float_as_uint(As[bf][m + 8][kq]);
                a[mi][2] = __float_as_uint(As[bf][m][kq + 4]);
                a[mi][3] = __float_as_uint(As[bf][m + 8][kq + 4]);
            }
#pragma unroll
            for (int ni = 0; ni < 4; ni++) {
                int p = wn + ni * 8 + (lane >> 2);
                bfr[ni][0] = __float_as_uint(Bs[bf][kq][p]);
                bfr[ni][1] = __float_as_uint(Bs[bf][kq + 4][p]);
            }
#pragma unroll
            for (int mi = 0; mi < 4; mi++)
#pragma unroll
                for (int ni = 0; ni < 4; ni++)
                    mma_tf32(acc[mi][ni], a[mi], bfr[ni]);
        }
        if (c < 15) {
            int nb = (c + 1) & 1;
            STS_STAGE(nb);
        }
    }
    #undef STS_STAGE

    // epilogue: BN + ReLU + scatter to [qkv][win][head][n][d]
    int winv[4][2], nn[4][2];
#pragma unroll
    for (int ni = 0; ni < 4; ni++)
#pragma unroll
        for (int e = 0; e < 2; e++) {
            int pin = pp0 + wn + ni * 8 + 2 * (lane & 3) + e;
            int row = pin / 192;
            int col = pin - row * 192;
            winv[ni][e] = b * 576 + (row >> 3) * 24 + (col >> 3);
            nn[ni][e]   = ((row & 7) << 3) + (col & 7);
        }
#pragma unroll
    for (int mi = 0; mi < 4; mi++) {
#pragma unroll
        for (int rh = 0; rh < 2; rh++) {
            int ol = wm + mi * 16 + (lane >> 2) + rh * 8;
            int o  = o0 + ol;
            float iv = sinv[ol], bz = sbz[ol];
            int qkv  = o >> 8;
            int head = (o >> 4) & 15;
            int d    = o & 15;
            float* basep = g_scratch + (size_t)qkv * QKV_STRIDE + head * 1024 + d;
#pragma unroll
            for (int ni = 0; ni < 4; ni++)
#pragma unroll
                for (int e = 0; e < 2; e++) {
                    float t = acc[mi][ni][rh * 2 + e] * iv + bz;
                    basep[winv[ni][e] * 16384 + nn[ni][e] * 16] = t > 0.f ? t : 0.f;
                }
        }
    }
}

// ---------------- attention: 4 windows x SAME head per block, 64 thr/unit --------------
__global__ __launch_bounds__(256) void attn_kernel(
    const float* __restrict__ rel_table,
    float* __restrict__ out_attn, float* __restrict__ out_avg)
{
    __shared__ __align__(16) float qt[4][1024];   // [unit][d*64 + n]
    __shared__ __align__(16) float kt[4][1024];   // [unit][d*64 + m]
    __shared__ float biash[226];                  // one head per block

    const int tid  = threadIdx.x;
    const int u    = tid >> 6;
    const int t    = tid & 63;
    const int head = blockIdx.x & 15;
    const int win  = (blockIdx.x >> 4) * 4 + u;

    const float* qg = g_scratch + (size_t)win * 16384 + head * 1024;
    const float* kg = qg + QKV_STRIDE;

#pragma unroll
    for (int d4 = 0; d4 < 4; d4++) {
        float4 v = *reinterpret_cast<const float4*>(&qg[t*16 + d4*4]);
        qt[u][(d4*4+0)*64 + t] = v.x;
        qt[u][(d4*4+1)*64 + t] = v.y;
        qt[u][(d4*4+2)*64 + t] = v.z;
        qt[u][(d4*4+3)*64 + t] = v.w;
        float4 kv = *reinterpret_cast<const float4*>(&kg[t*16 + d4*4]);
        kt[u][(d4*4+0)*64 + t] = kv.x;
        kt[u][(d4*4+1)*64 + t] = kv.y;
        kt[u][(d4*4+2)*64 + t] = kv.z;
        kt[u][(d4*4+3)*64 + t] = kv.w;
    }
    if (tid < 225) biash[tid] = rel_table[tid * 16 + head];
    __syncthreads();

    const int cc = t & 7;
    const int rr = t >> 3;

    float acc[8][8];
#pragma unroll
    for (int i = 0; i < 8; i++)
#pragma unroll
        for (int j = 0; j < 8; j++) acc[i][j] = 0.f;

    const float* qb = &qt[u][rr * 8];
    const float* kb = &kt[u][cc * 8];
#pragma unroll
    for (int d = 0; d < 16; d++) {
        float a[8], bb[8];
        *reinterpret_cast<float4*>(&a[0])  = *reinterpret_cast<const float4*>(&qb[d*64]);
        *reinterpret_cast<float4*>(&a[4])  = *reinterpret_cast<const float4*>(&qb[d*64 + 4]);
        *reinterpret_cast<float4*>(&bb[0]) = *reinterpret_cast<const float4*>(&kb[d*64]);
        *reinterpret_cast<float4*>(&bb[4]) = *reinterpret_cast<const float4*>(&kb[d*64 + 4]);
#pragma unroll
        for (int i = 0; i < 8; i++)
#pragma unroll
            for (int j = 0; j < 8; j++)
                acc[i][j] += a[i] * bb[j];
    }

    float b[15];
    {
        const float* bp = &biash[(rr - cc + 7) * 15];
#pragma unroll
        for (int k = 0; k < 15; k++) b[k] = bp[k];
    }
#pragma unroll
    for (int i = 0; i < 8; i++)
#pragma unroll
        for (int j = 0; j < 8; j++)
            acc[i][j] = acc[i][j] * 0.25f + b[i - j + 7];

#pragma unroll
    for (int j = 0; j < 8; j++) {
        float s = acc[0][j] + acc[1][j] + acc[2][j] + acc[3][j]
                + acc[4][j] + acc[5][j] + acc[6][j] + acc[7][j];
        s += __shfl_xor_sync(0xffffffffu, s, 8);
        s += __shfl_xor_sync(0xffffffffu, s, 16);
        if ((t & 31) < 8)
            atomicAdd(&out_avg[win * 64 + cc * 8 + j], s * (1.0f / 1024.0f));
    }

#pragma unroll
    for (int i = 0; i < 8; i++) {
        float mx = acc[i][0];
#pragma unroll
        for (int j = 1; j < 8; j++) mx = fmaxf(mx, acc[i][j]);
        mx = fmaxf(mx, __shfl_xor_sync(0xffffffffu, mx, 1));
        mx = fmaxf(mx, __shfl_xor_sync(0xffffffffu, mx, 2));
        mx = fmaxf(mx, __shfl_xor_sync(0xffffffffu, mx, 4));
        float sum = 0.f;
#pragma unroll
        for (int j = 0; j < 8; j++) { acc[i][j] = __expf(acc[i][j] - mx); sum += acc[i][j]; }
        sum += __shfl_xor_sync(0xffffffffu, sum, 1);
        sum += __shfl_xor_sync(0xffffffffu, sum, 2);
        sum += __shfl_xor_sync(0xffffffffu, sum, 4);
        float rinv = __frcp_rn(sum);
#pragma unroll
        for (int j = 0; j < 8; j++) acc[i][j] *= rinv;
    }

    float* ob = out_attn + ((size_t)(win * 16 + head) * 64 + rr * 8) * 64 + cc * 8;
#pragma unroll
    for (int i = 0; i < 8; i++) {
        float4 v0 = make_float4(acc[i][0], acc[i][1], acc[i][2], acc[i][3]);
        float4 v1 = make_float4(acc[i][4], acc[i][5], acc[i][6], acc[i][7]);
        *reinterpret_cast<float4*>(&ob[i * 64])     = v0;
        *reinterpret_cast<float4*>(&ob[i * 64 + 4]) = v1;
    }
}

extern "C" void kernel_launch(void* const* d_in, const int* in_sizes, int n_in,
                              void* d_out, int out_size) {
    const float* x     = (const float*)d_in[0];
    const float* w     = (const float*)d_in[1];
    const float* gamma = (const float*)d_in[2];
    const float* beta  = (const float*)d_in[3];
    const float* rmean = (const float*)d_in[4];
    const float* rvar  = (const float*)d_in[5];
    const float* rel   = (const float*)d_in[6];
    float* out     = (float*)d_out;
    float* out_avg = out + ATTN_ELEMS;

    cudaMemsetAsync(out_avg, 0, AVG_ELEMS * sizeof(float));
    proj_kernel<<<dim3(4, 576), 256>>>(x, w, gamma, beta, rmean, rvar);
    attn_kernel<<<4608, 256>>>(rel, out, out_avg);
}

// round 6
// speedup vs baseline: 1.0408x; 1.0408x over previous
#include <cuda_runtime.h>
#include <cstdint>

#define HW 36864
#define Cc 256
#define QKV_STRIDE 18874368   // 1152*16*64*16
#define ATTN_ELEMS 75497472   // 1152*16*64*64
#define AVG_ELEMS  73728      // 1152*64

__device__ __align__(16) float g_scratch[2 * QKV_STRIDE];   // q then k: [qkv][win][head][n][d]

__device__ __forceinline__ float tf32r(float x) {
    uint32_t u;
    asm("cvt.rna.tf32.f32 %0, %1;" : "=r"(u) : "f"(x));
    return __uint_as_float(u);
}

__device__ __forceinline__ void mma_tf32(float c[4], const uint32_t a[4], const uint32_t b[2]) {
    asm volatile(
        "mma.sync.aligned.m16n8k8.row.col.f32.tf32.tf32.f32 "
        "{%0,%1,%2,%3}, {%4,%5,%6,%7}, {%8,%9}, {%0,%1,%2,%3};"
        : "+f"(c[0]), "+f"(c[1]), "+f"(c[2]), "+f"(c[3])
        : "r"(a[0]), "r"(a[1]), "r"(a[2]), "r"(a[3]), "r"(b[0]), "r"(b[1]));
}

// ---------------- fused 1x1conv(GEMM, tf32 tensor) + BN + ReLU + window rearrange ------
// (R4 version — measured faster than the R5 pipelined variant)
__global__ __launch_bounds__(256) void proj_kernel(
    const float* __restrict__ x, const float* __restrict__ w,
    const float* __restrict__ gamma, const float* __restrict__ beta,
    const float* __restrict__ rmean, const float* __restrict__ rvar)
{
    __shared__ __align__(16) float As[128][36];
    __shared__ __align__(16) float Bs[32][136];
    __shared__ float sinv[128], sbz[128];

    const int tid  = threadIdx.x;
    const int warp = tid >> 5;
    const int lane = tid & 31;
    const int o0   = blockIdx.x * 128;
    const int pg0  = blockIdx.y * 128;
    const int b    = pg0 / HW;
    const int pp0  = pg0 - b * HW;
    const float* xb = x + (size_t)b * (Cc * HW);

    if (tid < 128) {
        int og = o0 + tid;
        float iv = gamma[og] * rsqrtf(rvar[og] + 1e-5f);
        sinv[tid] = iv;
        sbz[tid]  = beta[og] - rmean[og] * iv;
    }

    const int wm = (warp >> 2) * 64;
    const int wn = (warp & 3) * 32;

    float acc[4][4][4];
#pragma unroll
    for (int mi = 0; mi < 4; mi++)
#pragma unroll
        for (int ni = 0; ni < 4; ni++)
#pragma unroll
            for (int r = 0; r < 4; r++) acc[mi][ni][r] = 0.f;

    for (int c0 = 0; c0 < Cc; c0 += 32) {
        __syncthreads();
#pragma unroll
        for (int l = 0; l < 4; l++) {
            int idx = tid + l * 256;
            int o = idx >> 3, cg = idx & 7;
            float4 v = *reinterpret_cast<const float4*>(&w[(o0 + o) * Cc + c0 + cg * 4]);
            v.x = tf32r(v.x); v.y = tf32r(v.y); v.z = tf32r(v.z); v.w = tf32r(v.w);
            *reinterpret_cast<float4*>(&As[o][cg * 4]) = v;
        }
#pragma unroll
        for (int l = 0; l < 4; l++) {
            int idx = tid + l * 256;
            int r = idx >> 5, c4 = idx & 31;
            float4 v = *reinterpret_cast<const float4*>(&xb[(c0 + r) * HW + pp0 + c4 * 4]);
            v.x = tf32r(v.x); v.y = tf32r(v.y); v.z = tf32r(v.z); v.w = tf32r(v.w);
            *reinterpret_cast<float4*>(&Bs[r][c4 * 4]) = v;
        }
        __syncthreads();

#pragma unroll
        for (int kk = 0; kk < 4; kk++) {
            const int kq = kk * 8 + (lane & 3);
            uint32_t a[4][4], bf[4][2];
#pragma unroll
            for (int mi = 0; mi < 4; mi++) {
                int m = wm + mi * 16 + (lane >> 2);
                a[mi][0] = __float_as_uint(As[m][kq]);
                a[mi][1] = __float_as_uint(As[m + 8][kq]);
                a[mi][2] = __float_as_uint(As[m][kq + 4]);
                a[mi][3] = __float_as_uint(As[m + 8][kq + 4]);
            }
#pragma unroll
            for (int ni = 0; ni < 4; ni++) {
                int p = wn + ni * 8 + (lane >> 2);
                bf[ni][0] = __float_as_uint(Bs[kq][p]);
                bf[ni][1] = __float_as_uint(Bs[kq + 4][p]);
            }
#pragma unroll
            for (int mi = 0; mi < 4; mi++)
#pragma unroll
                for (int ni = 0; ni < 4; ni++)
                    mma_tf32(acc[mi][ni], a[mi], bf[ni]);
        }
    }

    int winv[4][2], nn[4][2];
#pragma unroll
    for (int ni = 0; ni < 4; ni++)
#pragma unroll
        for (int e = 0; e < 2; e++) {
            int pin = pp0 + wn + ni * 8 + 2 * (lane & 3) + e;
            int row = pin / 192;
            int col = pin - row * 192;
            winv[ni][e] = b * 576 + (row >> 3) * 24 + (col >> 3);
            nn[ni][e]   = ((row & 7) << 3) + (col & 7);
        }
#pragma unroll
    for (int mi = 0; mi < 4; mi++) {
#pragma unroll
        for (int rh = 0; rh < 2; rh++) {
            int ol = wm + mi * 16 + (lane >> 2) + rh * 8;
            int o  = o0 + ol;
            float iv = sinv[ol], bz = sbz[ol];
            int qkv  = o >> 8;
            int head = (o >> 4) & 15;
            int d    = o & 15;
            float* basep = g_scratch + (size_t)qkv * QKV_STRIDE + head * 1024 + d;
#pragma unroll
            for (int ni = 0; ni < 4; ni++)
#pragma unroll
                for (int e = 0; e < 2; e++) {
                    float t = acc[mi][ni][rh * 2 + e] * iv + bz;
                    basep[winv[ni][e] * 16384 + nn[ni][e] * 16] = t > 0.f ? t : 0.f;
                }
        }
    }
}

// ---------------- attention: 2 windows x SAME head per block, 128 thr/unit, 8x4 tile ---
__global__ __launch_bounds__(256, 3) void attn_kernel(
    const float* __restrict__ rel_table,
    float* __restrict__ out_attn, float* __restrict__ out_avg)
{
    __shared__ __align__(16) float qt[2][1024];   // [unit][d*64 + n]
    __shared__ __align__(16) float kt[2][1024];   // [unit][d*64 + m]
    __shared__ float biash[226];                  // one head per block

    const int tid  = threadIdx.x;
    const int u    = tid >> 7;
    const int t    = tid & 127;
    const int head = blockIdx.x & 15;
    const int win  = (blockIdx.x >> 4) * 2 + u;

    const float* qg = g_scratch + (size_t)win * 16384 + head * 1024;
    const float* kg = qg + QKV_STRIDE;

    // transpose-load q,k: thread t handles row n = t&63, d-half = (t>>6)*8
    {
        const int n    = t & 63;
        const int dh   = (t >> 6) * 8;
        float4 v0 = *reinterpret_cast<const float4*>(&qg[n * 16 + dh]);
        float4 v1 = *reinterpret_cast<const float4*>(&qg[n * 16 + dh + 4]);
        qt[u][(dh+0)*64 + n] = v0.x; qt[u][(dh+1)*64 + n] = v0.y;
        qt[u][(dh+2)*64 + n] = v0.z; qt[u][(dh+3)*64 + n] = v0.w;
        qt[u][(dh+4)*64 + n] = v1.x; qt[u][(dh+5)*64 + n] = v1.y;
        qt[u][(dh+6)*64 + n] = v1.z; qt[u][(dh+7)*64 + n] = v1.w;
        float4 k0 = *reinterpret_cast<const float4*>(&kg[n * 16 + dh]);
        float4 k1 = *reinterpret_cast<const float4*>(&kg[n * 16 + dh + 4]);
        kt[u][(dh+0)*64 + n] = k0.x; kt[u][(dh+1)*64 + n] = k0.y;
        kt[u][(dh+2)*64 + n] = k0.z; kt[u][(dh+3)*64 + n] = k0.w;
        kt[u][(dh+4)*64 + n] = k1.x; kt[u][(dh+5)*64 + n] = k1.y;
        kt[u][(dh+6)*64 + n] = k1.z; kt[u][(dh+7)*64 + n] = k1.w;
    }
    if (tid < 225) biash[tid] = rel_table[tid * 16 + head];
    __syncthreads();

    const int rr = t >> 4;   // row group: rows n = rr*8 + i   (0..7)
    const int cc = t & 15;   // col group: cols m = cc*4 + j   (0..15)

    float acc[8][4];
#pragma unroll
    for (int i = 0; i < 8; i++)
#pragma unroll
        for (int j = 0; j < 4; j++) acc[i][j] = 0.f;

    const float* qb = &qt[u][rr * 8];
    const float* kb = &kt[u][cc * 4];
#pragma unroll
    for (int d = 0; d < 16; d++) {
        float a[8], bb[4];
        *reinterpret_cast<float4*>(&a[0])  = *reinterpret_cast<const float4*>(&qb[d*64]);
        *reinterpret_cast<float4*>(&a[4])  = *reinterpret_cast<const float4*>(&qb[d*64 + 4]);
        *reinterpret_cast<float4*>(&bb[0]) = *reinterpret_cast<const float4*>(&kb[d*64]);
#pragma unroll
        for (int i = 0; i < 8; i++)
#pragma unroll
            for (int j = 0; j < 4; j++)
                acc[i][j] += a[i] * bb[j];
    }

    // bias: row n=rr*8+i -> y1=rr, x1=i; col m=cc*4+j -> y2=cc>>1, x2=(cc&1)*4+j
    float b[15];
    {
        const float* bp = &biash[(rr - (cc >> 1) + 7) * 15];
#pragma unroll
        for (int k = 0; k < 15; k++) b[k] = bp[k];
    }
    const int x2b = (cc & 1) * 4;
#pragma unroll
    for (int i = 0; i < 8; i++)
#pragma unroll
        for (int j = 0; j < 4; j++)
            acc[i][j] = acc[i][j] * 0.25f + b[i - (x2b + j) + 7];

    // avg column sums: xor 16 pairs rr^1 (16 rows), then quarter-warp atomics
#pragma unroll
    for (int j = 0; j < 4; j++) {
        float s = acc[0][j] + acc[1][j] + acc[2][j] + acc[3][j]
                + acc[4][j] + acc[5][j] + acc[6][j] + acc[7][j];
        s += __shfl_xor_sync(0xffffffffu, s, 16);
        if ((t & 16) == 0)
            atomicAdd(&out_avg[win * 64 + cc * 4 + j], s * (1.0f / 1024.0f));
    }

    // row softmax: reduce over the 16 cc lanes (xor 1,2,4,8)
#pragma unroll
    for (int i = 0; i < 8; i++) {
        float mx = fmaxf(fmaxf(acc[i][0], acc[i][1]), fmaxf(acc[i][2], acc[i][3]));
        mx = fmaxf(mx, __shfl_xor_sync(0xffffffffu, mx, 1));
        mx = fmaxf(mx, __shfl_xor_sync(0xffffffffu, mx, 2));
        mx = fmaxf(mx, __shfl_xor_sync(0xffffffffu, mx, 4));
        mx = fmaxf(mx, __shfl_xor_sync(0xffffffffu, mx, 8));
        float sum = 0.f;
#pragma unroll
        for (int j = 0; j < 4; j++) { acc[i][j] = __expf(acc[i][j] - mx); sum += acc[i][j]; }
        sum += __shfl_xor_sync(0xffffffffu, sum, 1);
        sum += __shfl_xor_sync(0xffffffffu, sum, 2);
        sum += __shfl_xor_sync(0xffffffffu, sum, 4);
        sum += __shfl_xor_sync(0xffffffffu, sum, 8);
        float rinv = __frcp_rn(sum);
#pragma unroll
        for (int j = 0; j < 4; j++) acc[i][j] *= rinv;
    }

    // store: rows rr*8+i, cols cc*4..+3 (16 lanes cover a full 256B row)
    float* ob = out_attn + ((size_t)(win * 16 + head) * 64 + rr * 8) * 64 + cc * 4;
#pragma unroll
    for (int i = 0; i < 8; i++)
        *reinterpret_cast<float4*>(&ob[i * 64]) =
            make_float4(acc[i][0], acc[i][1], acc[i][2], acc[i][3]);
}

extern "C" void kernel_launch(void* const* d_in, const int* in_sizes, int n_in,
                              void* d_out, int out_size) {
    const float* x     = (const float*)d_in[0];
    const float* w     = (const float*)d_in[1];
    const float* gamma = (const float*)d_in[2];
    const float* beta  = (const float*)d_in[3];
    const float* rmean = (const float*)d_in[4];
    const float* rvar  = (const float*)d_in[5];
    const float* rel   = (const float*)d_in[6];
    float* out     = (float*)d_out;
    float* out_avg = out + ATTN_ELEMS;

    cudaMemsetAsync(out_avg, 0, AVG_ELEMS * sizeof(float));
    proj_kernel<<<dim3(4, 576), 256>>>(x, w, gamma, beta, rmean, rvar);
    attn_kernel<<<9216, 256>>>(rel, out, out_avg);
}

// round 7
// speedup vs baseline: 1.2094x; 1.1620x over previous
#include <cuda_runtime.h>
#include <cstdint>

#define HW 36864
#define Cc 256
#define QKV_STRIDE 18874368   // 1152*16*64*16
#define ATTN_ELEMS 75497472   // 1152*16*64*64
#define AVG_ELEMS  73728      // 1152*64

// q: A-fragment layout [win*16+head][slice(4)][ks(2)][lane(32)][j(4)]
// k: B-fragment layout [win*16+head][ni(8)][ks(2)][lane(32)][e(2)]
__device__ __align__(16) float g_scratch[2 * QKV_STRIDE];

__device__ __forceinline__ float tf32r(float x) {
    uint32_t u;
    asm("cvt.rna.tf32.f32 %0, %1;" : "=r"(u) : "f"(x));
    return __uint_as_float(u);
}

__device__ __forceinline__ float ex2f(float x) {
    float y;
    asm("ex2.approx.ftz.f32 %0, %1;" : "=f"(y) : "f"(x));
    return y;
}

__device__ __forceinline__ void mma_tf32(float c[4], const uint32_t a[4], const uint32_t b[2]) {
    asm volatile(
        "mma.sync.aligned.m16n8k8.row.col.f32.tf32.tf32.f32 "
        "{%0,%1,%2,%3}, {%4,%5,%6,%7}, {%8,%9}, {%0,%1,%2,%3};"
        : "+f"(c[0]), "+f"(c[1]), "+f"(c[2]), "+f"(c[3])
        : "r"(a[0]), "r"(a[1]), "r"(a[2]), "r"(a[3]), "r"(b[0]), "r"(b[1]));
}

// ---------------- fused 1x1conv(GEMM, tf32 tensor) + BN + ReLU + frag-layout scatter ---
__global__ __launch_bounds__(256) void proj_kernel(
    const float* __restrict__ x, const float* __restrict__ w,
    const float* __restrict__ gamma, const float* __restrict__ beta,
    const float* __restrict__ rmean, const float* __restrict__ rvar)
{
    __shared__ __align__(16) float As[128][36];
    __shared__ __align__(16) float Bs[32][136];
    __shared__ float sinv[128], sbz[128];

    const int tid  = threadIdx.x;
    const int warp = tid >> 5;
    const int lane = tid & 31;
    const int o0   = blockIdx.x * 128;
    const int pg0  = blockIdx.y * 128;
    const int b    = pg0 / HW;
    const int pp0  = pg0 - b * HW;
    const float* xb = x + (size_t)b * (Cc * HW);

    if (tid < 128) {
        int og = o0 + tid;
        float iv = gamma[og] * rsqrtf(rvar[og] + 1e-5f);
        sinv[tid] = iv;
        sbz[tid]  = beta[og] - rmean[og] * iv;
    }

    const int wm = (warp >> 2) * 64;
    const int wn = (warp & 3) * 32;

    float acc[4][4][4];
#pragma unroll
    for (int mi = 0; mi < 4; mi++)
#pragma unroll
        for (int ni = 0; ni < 4; ni++)
#pragma unroll
            for (int r = 0; r < 4; r++) acc[mi][ni][r] = 0.f;

    for (int c0 = 0; c0 < Cc; c0 += 32) {
        __syncthreads();
#pragma unroll
        for (int l = 0; l < 4; l++) {
            int idx = tid + l * 256;
            int o = idx >> 3, cg = idx & 7;
            float4 v = *reinterpret_cast<const float4*>(&w[(o0 + o) * Cc + c0 + cg * 4]);
            v.x = tf32r(v.x); v.y = tf32r(v.y); v.z = tf32r(v.z); v.w = tf32r(v.w);
            *reinterpret_cast<float4*>(&As[o][cg * 4]) = v;
        }
#pragma unroll
        for (int l = 0; l < 4; l++) {
            int idx = tid + l * 256;
            int r = idx >> 5, c4 = idx & 31;
            float4 v = *reinterpret_cast<const float4*>(&xb[(c0 + r) * HW + pp0 + c4 * 4]);
            v.x = tf32r(v.x); v.y = tf32r(v.y); v.z = tf32r(v.z); v.w = tf32r(v.w);
            *reinterpret_cast<float4*>(&Bs[r][c4 * 4]) = v;
        }
        __syncthreads();

#pragma unroll
        for (int kk = 0; kk < 4; kk++) {
            const int kq = kk * 8 + (lane & 3);
            uint32_t a[4][4], bf[4][2];
#pragma unroll
            for (int mi = 0; mi < 4; mi++) {
                int m = wm + mi * 16 + (lane >> 2);
                a[mi][0] = __float_as_uint(As[m][kq]);
                a[mi][1] = __float_as_uint(As[m + 8][kq]);
                a[mi][2] = __float_as_uint(As[m][kq + 4]);
                a[mi][3] = __float_as_uint(As[m + 8][kq + 4]);
            }
#pragma unroll
            for (int ni = 0; ni < 4; ni++) {
                int p = wn + ni * 8 + (lane >> 2);
                bf[ni][0] = __float_as_uint(Bs[kq][p]);
                bf[ni][1] = __float_as_uint(Bs[kq + 4][p]);
            }
#pragma unroll
            for (int mi = 0; mi < 4; mi++)
#pragma unroll
                for (int ni = 0; ni < 4; ni++)
                    mma_tf32(acc[mi][ni], a[mi], bf[ni]);
        }
    }

    // epilogue: BN + ReLU + scatter into attn fragment layouts
    int winv[4][2], nn[4][2];
#pragma unroll
    for (int ni = 0; ni < 4; ni++)
#pragma unroll
        for (int e = 0; e < 2; e++) {
            int pin = pp0 + wn + ni * 8 + 2 * (lane & 3) + e;
            int row = pin / 192;
            int col = pin - row * 192;
            winv[ni][e] = b * 576 + (row >> 3) * 24 + (col >> 3);
            nn[ni][e]   = ((row & 7) << 3) + (col & 7);
        }
    const int lq = (lane >> 2) & 3;      // d & 3
    const int db = (lane >> 4) & 1;      // (d>>2) & 1
#pragma unroll
    for (int mi = 0; mi < 4; mi++) {
#pragma unroll
        for (int rh = 0; rh < 2; rh++) {     // rh = d>>3 (ks)
            int ol = wm + mi * 16 + (lane >> 2) + rh * 8;
            int o  = o0 + ol;
            float iv = sinv[ol], bz = sbz[ol];
            int qkv  = o >> 8;
            int head = (o >> 4) & 15;
            float* base = g_scratch + (size_t)qkv * QKV_STRIDE + head * 1024;
#pragma unroll
            for (int ni = 0; ni < 4; ni++)
#pragma unroll
                for (int e = 0; e < 2; e++) {
                    float t = acc[mi][ni][rh * 2 + e] * iv + bz;
                    t = t > 0.f ? t : 0.f;
                    int n = nn[ni][e];
                    size_t wb = (size_t)winv[ni][e] * 16384;
                    if (qkv == 0) {
                        t *= 0.36067376f;   // 0.25 * log2(e) folded into q
                        int off = ((n >> 4) * 2 + rh) * 128
                                + ((((n & 7) << 2) | lq) << 2)
                                + ((n >> 3) & 1) + db * 2;
                        base[wb + off] = t;
                    } else {
                        int off = ((n >> 3) * 2 + rh) * 64
                                + ((((n & 7) << 2) | lq) << 1) + db;
                        base[wb + off] = t;
                    }
                }
        }
    }
}

// ---------------- attention: warp = (win, head, 16-row slice), HMMA dots, log2 softmax --
__global__ __launch_bounds__(256, 3) void attn_kernel(
    const float* __restrict__ rel_table,
    float* __restrict__ out_attn, float* __restrict__ out_avg)
{
    __shared__ float biasl[232];   // bias * log2(e), one head per block

    const int tid  = threadIdx.x;
    const int w    = tid >> 5;
    const int lane = tid & 31;
    const int head = blockIdx.x & 15;
    const int wp   = blockIdx.x >> 4;

    if (tid < 225) biasl[tid] = rel_table[tid * 16 + head] * 1.4426950408f;
    __syncthreads();

    const int win   = wp * 2 + (w >> 2);
    const int slice = w & 3;
    const float* qb = g_scratch + (size_t)(win * 16 + head) * 1024;
    const float* kb = qb + QKV_STRIDE;

    // A fragments (q, this 16-row slice), coalesced LDG.128
    uint32_t a[2][4];
    *reinterpret_cast<float4*>(&a[0][0]) =
        *reinterpret_cast<const float4*>(qb + ((slice * 2 + 0) * 32 + lane) * 4);
    *reinterpret_cast<float4*>(&a[1][0]) =
        *reinterpret_cast<const float4*>(qb + ((slice * 2 + 1) * 32 + lane) * 4);

    float acc[8][4];
#pragma unroll
    for (int ni = 0; ni < 8; ni++) {
#pragma unroll
        for (int r = 0; r < 4; r++) acc[ni][r] = 0.f;
        float2 b0 = *reinterpret_cast<const float2*>(kb + ((ni * 2 + 0) * 32 + lane) * 2);
        float2 b1 = *reinterpret_cast<const float2*>(kb + ((ni * 2 + 1) * 32 + lane) * 2);
        uint32_t bf0[2] = { __float_as_uint(b0.x), __float_as_uint(b0.y) };
        uint32_t bf1[2] = { __float_as_uint(b1.x), __float_as_uint(b1.y) };
        mma_tf32(acc[ni], a[0], bf0);
        mma_tf32(acc[ni], a[1], bf1);
    }

    const int g  = lane >> 2;
    const int l3 = lane & 3;

    // bias (log2-scaled): rows y1 = slice*2 + h, x1 = g; cols y2 = ni, x2 = 2*l3+e
    const int X0 = g - 2 * l3 + 7;
#pragma unroll
    for (int ni = 0; ni < 8; ni++) {
        const float* r0 = &biasl[(slice * 2 - ni + 7) * 15];
        acc[ni][0] += r0[X0];
        acc[ni][1] += r0[X0 - 1];
        acc[ni][2] += r0[15 + X0];
        acc[ni][3] += r0[15 + X0 - 1];
    }

    // avg: column sums of pre-softmax dots (x = x' * ln2)
#pragma unroll
    for (int ni = 0; ni < 8; ni++)
#pragma unroll
        for (int e = 0; e < 2; e++) {
            float s = acc[ni][e] + acc[ni][2 + e];
            s += __shfl_xor_sync(0xffffffffu, s, 4);
            s += __shfl_xor_sync(0xffffffffu, s, 8);
            s += __shfl_xor_sync(0xffffffffu, s, 16);
            if (g == 0)
                atomicAdd(&out_avg[win * 64 + ni * 8 + 2 * l3 + e],
                          s * 6.7690154e-4f);   // ln2/1024
        }

    // row softmax in log2 domain (rows: h=0 -> slice*16+g, h=1 -> +8)
#pragma unroll
    for (int h = 0; h < 2; h++) {
        float mx = fmaxf(acc[0][2*h], acc[0][2*h+1]);
#pragma unroll
        for (int ni = 1; ni < 8; ni++)
            mx = fmaxf(mx, fmaxf(acc[ni][2*h], acc[ni][2*h+1]));
        mx = fmaxf(mx, __shfl_xor_sync(0xffffffffu, mx, 1));
        mx = fmaxf(mx, __shfl_xor_sync(0xffffffffu, mx, 2));
        float sum = 0.f;
#pragma unroll
        for (int ni = 0; ni < 8; ni++) {
            acc[ni][2*h]   = ex2f(acc[ni][2*h]   - mx);
            acc[ni][2*h+1] = ex2f(acc[ni][2*h+1] - mx);
            sum += acc[ni][2*h] + acc[ni][2*h+1];
        }
        sum += __shfl_xor_sync(0xffffffffu, sum, 1);
        sum += __shfl_xor_sync(0xffffffffu, sum, 2);
        float rinv = __frcp_rn(sum);
#pragma unroll
        for (int ni = 0; ni < 8; ni++) {
            acc[ni][2*h]   *= rinv;
            acc[ni][2*h+1] *= rinv;
        }
    }

    // store: rows slice*16+g and +8, cols ni*8 + 2*l3 (+e) — fully coalesced STG.64
    float* ob = out_attn + ((size_t)(win * 16 + head) * 64 + slice * 16 + g) * 64 + 2 * l3;
#pragma unroll
    for (int ni = 0; ni < 8; ni++) {
        *reinterpret_cast<float2*>(ob + ni * 8)          = make_float2(acc[ni][0], acc[ni][1]);
        *reinterpret_cast<float2*>(ob + 8 * 64 + ni * 8) = make_float2(acc[ni][2], acc[ni][3]);
    }
}

extern "C" void kernel_launch(void* const* d_in, const int* in_sizes, int n_in,
                              void* d_out, int out_size) {
    const float* x     = (const float*)d_in[0];
    const float* w     = (const float*)d_in[1];
    const float* gamma = (const float*)d_in[2];
    const float* beta  = (const float*)d_in[3];
    const float* rmean = (const float*)d_in[4];
    const float* rvar  = (const float*)d_in[5];
    const float* rel   = (const float*)d_in[6];
    float* out     = (float*)d_out;
    float* out_avg = out + ATTN_ELEMS;

    cudaMemsetAsync(out_avg, 0, AVG_ELEMS * sizeof(float));
    proj_kernel<<<dim3(4, 576), 256>>>(x, w, gamma, beta, rmean, rvar);
    attn_kernel<<<9216, 256>>>(rel, out, out_avg);
}

// round 8
// speedup vs baseline: 1.2181x; 1.0071x over previous
#include <cuda_runtime.h>
#include <cstdint>

#define HW 36864
#define Cc 256
#define QKV_STRIDE 18874368   // 1152*16*64*16
#define ATTN_ELEMS 75497472   // 1152*16*64*64
#define AVG_ELEMS  73728      // 1152*64

// q: A-fragment layout [win*16+head][slice(4)][ks(2)][lane(32)][j(4)]
// k: B-fragment layout [win*16+head][ni(8)][ks(2)][lane(32)][e(2)]
__device__ __align__(16) float g_scratch[2 * QKV_STRIDE];

__device__ __forceinline__ float tf32r(float x) {
    uint32_t u;
    asm("cvt.rna.tf32.f32 %0, %1;" : "=r"(u) : "f"(x));
    return __uint_as_float(u);
}

__device__ __forceinline__ float ex2f(float x) {
    float y;
    asm("ex2.approx.ftz.f32 %0, %1;" : "=f"(y) : "f"(x));
    return y;
}

__device__ __forceinline__ void mma_tf32(float c[4], const uint32_t a[4], const uint32_t b[2]) {
    asm volatile(
        "mma.sync.aligned.m16n8k8.row.col.f32.tf32.tf32.f32 "
        "{%0,%1,%2,%3}, {%4,%5,%6,%7}, {%8,%9}, {%0,%1,%2,%3};"
        : "+f"(c[0]), "+f"(c[1]), "+f"(c[2]), "+f"(c[3])
        : "r"(a[0]), "r"(a[1]), "r"(a[2]), "r"(a[3]), "r"(b[0]), "r"(b[1]));
}

// ---------------- fused 1x1conv(GEMM, tf32 tensor) + BN + ReLU + frag-layout scatter ---
__global__ __launch_bounds__(256) void proj_kernel(
    const float* __restrict__ x, const float* __restrict__ w,
    const float* __restrict__ gamma, const float* __restrict__ beta,
    const float* __restrict__ rmean, const float* __restrict__ rvar)
{
    __shared__ __align__(16) float As[128][36];
    __shared__ __align__(16) float Bs[32][136];
    __shared__ float sinv[128], sbz[128];

    const int tid  = threadIdx.x;
    const int warp = tid >> 5;
    const int lane = tid & 31;
    const int o0   = blockIdx.x * 128;
    const int pg0  = blockIdx.y * 128;
    const int b    = pg0 / HW;
    const int pp0  = pg0 - b * HW;
    const float* xb = x + (size_t)b * (Cc * HW);

    if (tid < 128) {
        int og = o0 + tid;
        float iv = gamma[og] * rsqrtf(rvar[og] + 1e-5f);
        sinv[tid] = iv;
        sbz[tid]  = beta[og] - rmean[og] * iv;
    }

    const int wm = (warp >> 2) * 64;
    const int wn = (warp & 3) * 32;

    float acc[4][4][4];
#pragma unroll
    for (int mi = 0; mi < 4; mi++)
#pragma unroll
        for (int ni = 0; ni < 4; ni++)
#pragma unroll
            for (int r = 0; r < 4; r++) acc[mi][ni][r] = 0.f;

    for (int c0 = 0; c0 < Cc; c0 += 32) {
        __syncthreads();
#pragma unroll
        for (int l = 0; l < 4; l++) {
            int idx = tid + l * 256;
            int o = idx >> 3, cg = idx & 7;
            float4 v = *reinterpret_cast<const float4*>(&w[(o0 + o) * Cc + c0 + cg * 4]);
            v.x = tf32r(v.x); v.y = tf32r(v.y); v.z = tf32r(v.z); v.w = tf32r(v.w);
            *reinterpret_cast<float4*>(&As[o][cg * 4]) = v;
        }
#pragma unroll
        for (int l = 0; l < 4; l++) {
            int idx = tid + l * 256;
            int r = idx >> 5, c4 = idx & 31;
            float4 v = *reinterpret_cast<const float4*>(&xb[(c0 + r) * HW + pp0 + c4 * 4]);
            v.x = tf32r(v.x); v.y = tf32r(v.y); v.z = tf32r(v.z); v.w = tf32r(v.w);
            *reinterpret_cast<float4*>(&Bs[r][c4 * 4]) = v;
        }
        __syncthreads();

#pragma unroll
        for (int kk = 0; kk < 4; kk++) {
            const int kq = kk * 8 + (lane & 3);
            uint32_t a[4][4], bf[4][2];
#pragma unroll
            for (int mi = 0; mi < 4; mi++) {
                int m = wm + mi * 16 + (lane >> 2);
                a[mi][0] = __float_as_uint(As[m][kq]);
                a[mi][1] = __float_as_uint(As[m + 8][kq]);
                a[mi][2] = __float_as_uint(As[m][kq + 4]);
                a[mi][3] = __float_as_uint(As[m + 8][kq + 4]);
            }
#pragma unroll
            for (int ni = 0; ni < 4; ni++) {
                int p = wn + ni * 8 + (lane >> 2);
                bf[ni][0] = __float_as_uint(Bs[kq][p]);
                bf[ni][1] = __float_as_uint(Bs[kq + 4][p]);
            }
#pragma unroll
            for (int mi = 0; mi < 4; mi++)
#pragma unroll
                for (int ni = 0; ni < 4; ni++)
                    mma_tf32(acc[mi][ni], a[mi], bf[ni]);
        }
    }

    // epilogue: BN + ReLU + scatter into attn fragment layouts
    int winv[4][2], nn[4][2];
#pragma unroll
    for (int ni = 0; ni < 4; ni++)
#pragma unroll
        for (int e = 0; e < 2; e++) {
            int pin = pp0 + wn + ni * 8 + 2 * (lane & 3) + e;
            int row = pin / 192;
            int col = pin - row * 192;
            winv[ni][e] = b * 576 + (row >> 3) * 24 + (col >> 3);
            nn[ni][e]   = ((row & 7) << 3) + (col & 7);
        }
    const int lq = (lane >> 2) & 3;      // d & 3
    const int db = (lane >> 4) & 1;      // (d>>2) & 1
#pragma unroll
    for (int mi = 0; mi < 4; mi++) {
#pragma unroll
        for (int rh = 0; rh < 2; rh++) {     // rh = d>>3 (ks)
            int ol = wm + mi * 16 + (lane >> 2) + rh * 8;
            int o  = o0 + ol;
            float iv = sinv[ol], bz = sbz[ol];
            int qkv  = o >> 8;
            int head = (o >> 4) & 15;
            float* base = g_scratch + (size_t)qkv * QKV_STRIDE + head * 1024;
#pragma unroll
            for (int ni = 0; ni < 4; ni++)
#pragma unroll
                for (int e = 0; e < 2; e++) {
                    float t = acc[mi][ni][rh * 2 + e] * iv + bz;
                    t = t > 0.f ? t : 0.f;
                    int n = nn[ni][e];
                    size_t wb = (size_t)winv[ni][e] * 16384;
                    if (qkv == 0) {
                        t *= 0.36067376f;   // 0.25 * log2(e) folded into q
                        int off = ((n >> 4) * 2 + rh) * 128
                                + ((((n & 7) << 2) | lq) << 2)
                                + ((n >> 3) & 1) + db * 2;
                        base[wb + off] = t;
                    } else {
                        int off = ((n >> 3) * 2 + rh) * 64
                                + ((((n & 7) << 2) | lq) << 1) + db;
                        base[wb + off] = t;
                    }
                }
        }
    }
}

// ---------------- attention: warp = (win, head, 16-row slice), HMMA dots, log2 softmax --
__global__ __launch_bounds__(256, 3) void attn_kernel(
    const float* __restrict__ rel_table,
    float* __restrict__ out_attn, float* __restrict__ out_avg)
{
    __shared__ float biasl[232];   // bias * log2(e), one head per block

    const int tid  = threadIdx.x;
    const int w    = tid >> 5;
    const int lane = tid & 31;
    const int head = blockIdx.x & 15;
    const int wp   = blockIdx.x >> 4;

    if (tid < 225) biasl[tid] = rel_table[tid * 16 + head] * 1.4426950408f;
    __syncthreads();

    const int win   = wp * 2 + (w >> 2);
    const int slice = w & 3;
    const float* qb = g_scratch + (size_t)(win * 16 + head) * 1024;
    const float* kb = qb + QKV_STRIDE;

    // A fragments (q, this 16-row slice), coalesced LDG.128
    uint32_t a[2][4];
    *reinterpret_cast<float4*>(&a[0][0]) =
        *reinterpret_cast<const float4*>(qb + ((slice * 2 + 0) * 32 + lane) * 4);
    *reinterpret_cast<float4*>(&a[1][0]) =
        *reinterpret_cast<const float4*>(qb + ((slice * 2 + 1) * 32 + lane) * 4);

    float acc[8][4];
#pragma unroll
    for (int ni = 0; ni < 8; ni++) {
#pragma unroll
        for (int r = 0; r < 4; r++) acc[ni][r] = 0.f;
        float2 b0 = *reinterpret_cast<const float2*>(kb + ((ni * 2 + 0) * 32 + lane) * 2);
        float2 b1 = *reinterpret_cast<const float2*>(kb + ((ni * 2 + 1) * 32 + lane) * 2);
        uint32_t bf0[2] = { __float_as_uint(b0.x), __float_as_uint(b0.y) };
        uint32_t bf1[2] = { __float_as_uint(b1.x), __float_as_uint(b1.y) };
        mma_tf32(acc[ni], a[0], bf0);
        mma_tf32(acc[ni], a[1], bf1);
    }

    const int g  = lane >> 2;
    const int l3 = lane & 3;

    // bias (log2-scaled): rows y1 = slice*2 + h, x1 = g; cols y2 = ni, x2 = 2*l3+e
    const int X0 = g - 2 * l3 + 7;
#pragma unroll
    for (int ni = 0; ni < 8; ni++) {
        const float* r0 = &biasl[(slice * 2 - ni + 7) * 15];
        acc[ni][0] += r0[X0];
        acc[ni][1] += r0[X0 - 1];
        acc[ni][2] += r0[15 + X0];
        acc[ni][3] += r0[15 + X0 - 1];
    }

    // avg: column sums of pre-softmax dots (x = x' * ln2)
#pragma unroll
    for (int ni = 0; ni < 8; ni++)
#pragma unroll
        for (int e = 0; e < 2; e++) {
            float s = acc[ni][e] + acc[ni][2 + e];
            s += __shfl_xor_sync(0xffffffffu, s, 4);
            s += __shfl_xor_sync(0xffffffffu, s, 8);
            s += __shfl_xor_sync(0xffffffffu, s, 16);
            if (g == 0)
                atomicAdd(&out_avg[win * 64 + ni * 8 + 2 * l3 + e],
                          s * 6.7690154e-4f);   // ln2/1024
        }

    // row softmax in log2 domain (rows: h=0 -> slice*16+g, h=1 -> +8)
#pragma unroll
    for (int h = 0; h < 2; h++) {
        float mx = fmaxf(acc[0][2*h], acc[0][2*h+1]);
#pragma unroll
        for (int ni = 1; ni < 8; ni++)
            mx = fmaxf(mx, fmaxf(acc[ni][2*h], acc[ni][2*h+1]));
        mx = fmaxf(mx, __shfl_xor_sync(0xffffffffu, mx, 1));
        mx = fmaxf(mx, __shfl_xor_sync(0xffffffffu, mx, 2));
        float sum = 0.f;
#pragma unroll
        for (int ni = 0; ni < 8; ni++) {
            acc[ni][2*h]   = ex2f(acc[ni][2*h]   - mx);
            acc[ni][2*h+1] = ex2f(acc[ni][2*h+1] - mx);
            sum += acc[ni][2*h] + acc[ni][2*h+1];
        }
        sum += __shfl_xor_sync(0xffffffffu, sum, 1);
        sum += __shfl_xor_sync(0xffffffffu, sum, 2);
        float rinv = __frcp_rn(sum);
#pragma unroll
        for (int ni = 0; ni < 8; ni++) {
            acc[ni][2*h]   *= rinv;
            acc[ni][2*h+1] *= rinv;
        }
    }

    // store: rows slice*16+g and +8, cols ni*8 + 2*l3 (+e) — fully coalesced STG.64
    float* ob = out_attn + ((size_t)(win * 16 + head) * 64 + slice * 16 + g) * 64 + 2 * l3;
#pragma unroll
    for (int ni = 0; ni < 8; ni++) {
        *reinterpret_cast<float2*>(ob + ni * 8)          = make_float2(acc[ni][0], acc[ni][1]);
        *reinterpret_cast<float2*>(ob + 8 * 64 + ni * 8) = make_float2(acc[ni][2], acc[ni][3]);
    }
}

extern "C" void kernel_launch(void* const* d_in, const int* in_sizes, int n_in,
                              void* d_out, int out_size) {
    const float* x     = (const float*)d_in[0];
    const float* w     = (const float*)d_in[1];
    const float* gamma = (const float*)d_in[2];
    const float* beta  = (const float*)d_in[3];
    const float* rmean = (const float*)d_in[4];
    const float* rvar  = (const float*)d_in[5];
    const float* rel   = (const float*)d_in[6];
    float* out     = (float*)d_out;
    float* out_avg = out + ATTN_ELEMS;

    cudaMemsetAsync(out_avg, 0, AVG_ELEMS * sizeof(float));
    proj_kernel<<<dim3(4, 576), 256>>>(x, w, gamma, beta, rmean, rvar);
    attn_kernel<<<9216, 256>>>(rel, out, out_avg);
}

// round 10
// speedup vs baseline: 1.5005x; 1.2319x over previous
#include <cuda_runtime.h>
#include <cuda_fp16.h>
#include <cstdint>

#define HW 36864
#define Cc 256
#define QKV_STRIDE 18874368   // halves: 1152*16*64*16
#define ATTN_ELEMS 75497472   // 1152*16*64*64
#define AVG_ELEMS  73728      // 1152*64

// fp16 fragment scratch:
// q: A-frag (m16n8k16) layout [win*16+head][slice(4)][lane(32)][h(8)]   halves
// k: B-frag layout            [win*16+head][ni(8)][lane(32)][h(4)]     halves
__device__ __align__(16) __half g_scratch[2 * QKV_STRIDE];

__device__ __forceinline__ float ex2f(float x) {
    float y;
    asm("ex2.approx.ftz.f32 %0, %1;" : "=f"(y) : "f"(x));
    return y;
}

__device__ __forceinline__ void mma_f16(float c[4], const uint32_t a[4], const uint32_t b[2]) {
    asm volatile(
        "mma.sync.aligned.m16n8k16.row.col.f32.f16.f16.f32 "
        "{%0,%1,%2,%3}, {%4,%5,%6,%7}, {%8,%9}, {%0,%1,%2,%3};"
        : "+f"(c[0]), "+f"(c[1]), "+f"(c[2]), "+f"(c[3])
        : "r"(a[0]), "r"(a[1]), "r"(a[2]), "r"(a[3]), "r"(b[0]), "r"(b[1]));
}

// ---------------- fused 1x1conv (fp16 HMMA GEMM) + BN + ReLU + frag-layout scatter -----
// C[o,p] = sum_c W[o,c] * X[b,c,p]   M=512(o) N=73728(p) K=256
// Block 128x128, 8 warps (2x4), warp 64x32 = 4x4 m16n8k16 frags, K-chunk 64.
__global__ __launch_bounds__(256) void proj_kernel(
    const float* __restrict__ x, const float* __restrict__ w,
    const float* __restrict__ gamma, const float* __restrict__ beta,
    const float* __restrict__ rmean, const float* __restrict__ rvar)
{
    __shared__ __align__(16) __half  As[128][72];    // [o][k], 72-halves stride (bank-clean)
    __shared__ __align__(16) __half2 Bs2[32][136];   // [k/2][p], lo=even k, hi=odd k
    __shared__ float sinv[128], sbz[128];

    const int tid  = threadIdx.x;
    const int warp = tid >> 5;
    const int lane = tid & 31;
    const int o0   = blockIdx.x * 128;
    const int pg0  = blockIdx.y * 128;
    const int b    = pg0 / HW;               // tile never crosses batch
    const int pp0  = pg0 - b * HW;
    const float* xb = x + (size_t)b * (Cc * HW);

    if (tid < 128) {
        int og = o0 + tid;
        float iv = gamma[og] * rsqrtf(rvar[og] + 1e-5f);
        sinv[tid] = iv;
        sbz[tid]  = beta[og] - rmean[og] * iv;
    }

    const int g  = lane >> 2;
    const int l3 = lane & 3;
    const int wm = (warp >> 2) * 64;
    const int wn = (warp & 3) * 32;

    float acc[4][4][4];
#pragma unroll
    for (int mi = 0; mi < 4; mi++)
#pragma unroll
        for (int ni = 0; ni < 4; ni++)
#pragma unroll
            for (int r = 0; r < 4; r++) acc[mi][ni][r] = 0.f;

    for (int c0 = 0; c0 < Cc; c0 += 64) {
        __syncthreads();
        // W tile: 128 o x 64 k  -> As halves
#pragma unroll
        for (int l = 0; l < 8; l++) {
            int idx = tid + l * 256;
            int o = idx >> 4, kq = idx & 15;
            float4 v = *reinterpret_cast<const float4*>(&w[(o0 + o) * Cc + c0 + kq * 4]);
            __half2 h0 = __floats2half2_rn(v.x, v.y);
            __half2 h1 = __floats2half2_rn(v.z, v.w);
            __half2 hp[2] = {h0, h1};
            *reinterpret_cast<uint2*>(&As[o][kq * 4]) = *reinterpret_cast<uint2*>(hp);
        }
        // X tile: 64 k x 128 p -> Bs2 (pack k-even/k-odd into half2)
#pragma unroll
        for (int l = 0; l < 4; l++) {
            int idx = tid + l * 256;
            int kp = idx >> 5, pq = idx & 31;
            const float* xr = xb + (size_t)(c0 + 2 * kp) * HW + pp0 + pq * 4;
            float4 x0 = *reinterpret_cast<const float4*>(xr);
            float4 x1 = *reinterpret_cast<const float4*>(xr + HW);
            __half2 hp[4] = {
                __floats2half2_rn(x0.x, x1.x), __floats2half2_rn(x0.y, x1.y),
                __floats2half2_rn(x0.z, x1.z), __floats2half2_rn(x0.w, x1.w)};
            *reinterpret_cast<float4*>(&Bs2[kp][pq * 4]) = *reinterpret_cast<float4*>(hp);
        }
        __syncthreads();

#pragma unroll
        for (int s = 0; s < 4; s++) {        // 4 x k16 steps per 64-chunk
            uint32_t a[4][4], bf[4][2];
#pragma unroll
            for (int mi = 0; mi < 4; mi++) {
                int m = wm + mi * 16 + g;
                int k = s * 16 + 2 * l3;
                a[mi][0] = *reinterpret_cast<const uint32_t*>(&As[m][k]);
                a[mi][1] = *reinterpret_cast<const uint32_t*>(&As[m + 8][k]);
                a[mi][2] = *reinterpret_cast<const uint32_t*>(&As[m][k + 8]);
                a[mi][3] = *reinterpret_cast<const uint32_t*>(&As[m + 8][k + 8]);
            }
#pragma unroll
            for (int ni = 0; ni < 4; ni++) {
                int p = wn + ni * 8 + g;
                bf[ni][0] = *reinterpret_cast<const uint32_t*>(&Bs2[s * 8 + l3][p]);
                bf[ni][1] = *reinterpret_cast<const uint32_t*>(&Bs2[s * 8 + l3 + 4][p]);
            }
#pragma unroll
            for (int mi = 0; mi < 4; mi++)
#pragma unroll
                for (int ni = 0; ni < 4; ni++)
                    mma_f16(acc[mi][ni], a[mi], bf[ni]);
        }
    }

    // epilogue: BN + ReLU + scatter into fp16 attn fragment layouts
    int winv[4][2], nn[4][2];
#pragma unroll
    for (int ni = 0; ni < 4; ni++)
#pragma unroll
        for (int e = 0; e < 2; e++) {
            int pin = pp0 + wn + ni * 8 + 2 * l3 + e;
            int row = pin / 192;
            int col = pin - row * 192;
            winv[ni][e] = b * 576 + (row >> 3) * 24 + (col >> 3);
            nn[ni][e]   = ((row & 7) << 3) + (col & 7);
        }
#pragma unroll
    for (int mi = 0; mi < 4; mi++) {
#pragma unroll
        for (int rh = 0; rh < 2; rh++) {
            int ol = wm + mi * 16 + g + rh * 8;
            int o  = o0 + ol;
            float iv = sinv[ol], bz = sbz[ol];
            int qkv  = o >> 8;
            int head = (o >> 4) & 15;
            int d    = o & 15;
            int dl = (d >> 1) & 3, de = d & 1, dh = d >> 3;
            __half* gb = g_scratch + (size_t)qkv * QKV_STRIDE + head * 1024;
#pragma unroll
            for (int ni = 0; ni < 4; ni++)
#pragma unroll
                for (int e = 0; e < 2; e++) {
                    float t = acc[mi][ni][rh * 2 + e] * iv + bz;
                    t = t > 0.f ? t : 0.f;
                    int n = nn[ni][e];
                    int off;
                    if (qkv == 0) {
                        t *= 0.36067376f;   // 0.25 * log2(e) folded into q
                        off = (n >> 4) * 256 + ((((n & 7) << 2) | dl) << 3)
                            + (((n >> 3) & 1) << 1) + de + (dh << 2);
                    } else {
                        off = (n >> 3) * 128 + ((((n & 7) << 2) | dl) << 2)
                            + de + (dh << 1);
                    }
                    gb[(size_t)winv[ni][e] * 16384 + off] = __float2half_rn(t);
                }
        }
    }
}

// ---------------- attention: warp = (win, head, 16-row slice), fp16 HMMA dots ----------
__global__ __launch_bounds__(256, 4) void attn_kernel(
    const float* __restrict__ rel_table,
    float* __restrict__ out_attn, float* __restrict__ out_avg)
{
    __shared__ float biasl[232];   // bias * log2(e), one head per block

    const int tid  = threadIdx.x;
    const int w    = tid >> 5;
    const int lane = tid & 31;
    const int head = blockIdx.x & 15;
    const int wp   = blockIdx.x >> 4;

    if (tid < 225) biasl[tid] = rel_table[tid * 16 + head] * 1.4426950408f;
    __syncthreads();

    const int win   = wp * 2 + (w >> 2);
    const int slice = w & 3;
    const __half* qb = g_scratch + (size_t)(win * 16 + head) * 1024;
    const __half* kb = qb + QKV_STRIDE;

    // A fragment (q, this 16-row slice): one LDG.128
    uint4 av = *reinterpret_cast<const uint4*>(qb + slice * 256 + lane * 8);
    uint32_t a[4] = {av.x, av.y, av.z, av.w};

    float acc[8][4];
#pragma unroll
    for (int ni = 0; ni < 8; ni++) {
#pragma unroll
        for (int r = 0; r < 4; r++) acc[ni][r] = 0.f;
        uint2 bv = *reinterpret_cast<const uint2*>(kb + ni * 128 + lane * 4);
        uint32_t bf[2] = {bv.x, bv.y};
        mma_f16(acc[ni], a, bf);
    }

    const int g  = lane >> 2;
    const int l3 = lane & 3;

    // bias (log2-scaled): rows y1 = slice*2 + h, x1 = g; cols y2 = ni, x2 = 2*l3+e
    const int X0 = g - 2 * l3 + 7;
#pragma unroll
    for (int ni = 0; ni < 8; ni++) {
        const float* r0 = &biasl[(slice * 2 - ni + 7) * 15];
        acc[ni][0] += r0[X0];
        acc[ni][1] += r0[X0 - 1];
        acc[ni][2] += r0[15 + X0];
        acc[ni][3] += r0[15 + X0 - 1];
    }

    // avg: column sums of pre-softmax dots (x = x' * ln2)
#pragma unroll
    for (int ni = 0; ni < 8; ni++)
#pragma unroll
        for (int e = 0; e < 2; e++) {
            float s = acc[ni][e] + acc[ni][2 + e];
            s += __shfl_xor_sync(0xffffffffu, s, 4);
            s += __shfl_xor_sync(0xffffffffu, s, 8);
            s += __shfl_xor_sync(0xffffffffu, s, 16);
            if (g == 0)
                atomicAdd(&out_avg[win * 64 + ni * 8 + 2 * l3 + e],
                          s * 6.7690154e-4f);   // ln2/1024
        }

    // row softmax in log2 domain
#pragma unroll
    for (int h = 0; h < 2; h++) {
        float mx = fmaxf(acc[0][2*h], acc[0][2*h+1]);
#pragma unroll
        for (int ni = 1; ni < 8; ni++)
            mx = fmaxf(mx, fmaxf(acc[ni][2*h], acc[ni][2*h+1]));
        mx = fmaxf(mx, __shfl_xor_sync(0xffffffffu, mx, 1));
        mx = fmaxf(mx, __shfl_xor_sync(0xffffffffu, mx, 2));
        float sum = 0.f;
#pragma unroll
        for (int ni = 0; ni < 8; ni++) {
            acc[ni][2*h]   = ex2f(acc[ni][2*h]   - mx);
            acc[ni][2*h+1] = ex2f(acc[ni][2*h+1] - mx);
            sum += acc[ni][2*h] + acc[ni][2*h+1];
        }
        sum += __shfl_xor_sync(0xffffffffu, sum, 1);
        sum += __shfl_xor_sync(0xffffffffu, sum, 2);
        float rinv = __frcp_rn(sum);
#pragma unroll
        for (int ni = 0; ni < 8; ni++) {
            acc[ni][2*h]   *= rinv;
            acc[ni][2*h+1] *= rinv;
        }
    }

    // store: rows slice*16+g and +8, cols ni*8 + 2*l3 (+e)
    float* ob = out_attn + ((size_t)(win * 16 + head) * 64 + slice * 16 + g) * 64 + 2 * l3;
#pragma unroll
    for (int ni = 0; ni < 8; ni++) {
        *reinterpret_cast<float2*>(ob + ni * 8)          = make_float2(acc[ni][0], acc[ni][1]);
        *reinterpret_cast<float2*>(ob + 8 * 64 + ni * 8) = make_float2(acc[ni][2], acc[ni][3]);
    }
}

extern "C" void kernel_launch(void* const* d_in, const int* in_sizes, int n_in,
                              void* d_out, int out_size) {
    const float* x     = (const float*)d_in[0];
    const float* w     = (const float*)d_in[1];
    const float* gamma = (const float*)d_in[2];
    const float* beta  = (const float*)d_in[3];
    const float* rmean = (const float*)d_in[4];
    const float* rvar  = (const float*)d_in[5];
    const float* rel   = (const float*)d_in[6];
    float* out     = (float*)d_out;
    float* out_avg = out + ATTN_ELEMS;

    cudaMemsetAsync(out_avg, 0, AVG_ELEMS * sizeof(float));
    proj_kernel<<<dim3(4, 576), 256>>>(x, w, gamma, beta, rmean, rvar);
    attn_kernel<<<9216, 256>>>(rel, out, out_avg);
}

// round 11
// speedup vs baseline: 1.5149x; 1.0096x over previous
#include <cuda_runtime.h>
#include <cuda_fp16.h>
#include <cstdint>

#define HW 36864
#define Cc 256
#define QKV_STRIDE 18874368   // halves: 1152*16*64*16
#define ATTN_ELEMS 75497472   // 1152*16*64*64
#define AVG_ELEMS  73728      // 1152*64

// fp16 fragment scratch:
// q: A-frag (m16n8k16) layout [win*16+head][slice(4)][lane(32)][h(8)]   halves
// k: B-frag layout            [win*16+head][ni(8)][lane(32)][h(4)]     halves
__device__ __align__(16) __half g_scratch[2 * QKV_STRIDE];

__device__ __forceinline__ float ex2f(float x) {
    float y;
    asm("ex2.approx.ftz.f32 %0, %1;" : "=f"(y) : "f"(x));
    return y;
}
__device__ __forceinline__ uint32_t smem_u32(const void* p) {
    uint32_t a;
    asm("{ .reg .u64 t; cvta.to.shared.u64 t, %1; cvt.u32.u64 %0, t; }" : "=r"(a) : "l"(p));
    return a;
}
__device__ __forceinline__ void mma_f16(float c[4], const uint32_t a[4], const uint32_t b[2]) {
    asm volatile(
        "mma.sync.aligned.m16n8k16.row.col.f32.f16.f16.f32 "
        "{%0,%1,%2,%3}, {%4,%5,%6,%7}, {%8,%9}, {%0,%1,%2,%3};"
        : "+f"(c[0]), "+f"(c[1]), "+f"(c[2]), "+f"(c[3])
        : "r"(a[0]), "r"(a[1]), "r"(a[2]), "r"(a[3]), "r"(b[0]), "r"(b[1]));
}
#define CP_ASYNC16(d, s) \
    asm volatile("cp.async.cg.shared.global [%0], [%1], 16;" :: "r"(d), "l"(s) : "memory")
#define CP_COMMIT()  asm volatile("cp.async.commit_group;" ::: "memory")
#define CP_WAIT0()   asm volatile("cp.async.wait_group 0;" ::: "memory")

#define AS_BYTES 20480          // [2][128][40] halves
#define BS_BYTES 33792          // [2][32][132] floats
#define PROJ_SMEM (AS_BYTES + BS_BYTES + 1024)

// ---------------- fused 1x1conv (fp16 HMMA, cp.async pipelined) + BN + ReLU + scatter --
// C[o,p] = sum_c W[o,c] * X[b,c,p]   M=512(o) N=73728(p) K=256
// Block 128x128, 8 warps (2x4), warp 64x32 = 4x4 m16n8k16 frags, K-chunk 32, 8 chunks.
__global__ __launch_bounds__(256, 2) void proj_kernel(
    const float* __restrict__ x, const float* __restrict__ w,
    const float* __restrict__ gamma, const float* __restrict__ beta,
    const float* __restrict__ rmean, const float* __restrict__ rvar)
{
    extern __shared__ __align__(16) char dsm[];
    __half (*As)[128][40] = reinterpret_cast<__half(*)[128][40]>(dsm);
    float  (*Bs)[32][132] = reinterpret_cast<float(*)[32][132]>(dsm + AS_BYTES);
    float* sinv = reinterpret_cast<float*>(dsm + AS_BYTES + BS_BYTES);
    float* sbz  = sinv + 128;

    const int tid  = threadIdx.x;
    const int warp = tid >> 5;
    const int lane = tid & 31;
    const int o0   = blockIdx.x * 128;
    const int pg0  = blockIdx.y * 128;
    const int b    = pg0 / HW;               // tile never crosses batch
    const int pp0  = pg0 - b * HW;
    const float* xb = x + (size_t)b * (Cc * HW);

    if (tid < 128) {
        int og = o0 + tid;
        float iv = gamma[og] * rsqrtf(rvar[og] + 1e-5f);
        sinv[tid] = iv;
        sbz[tid]  = beta[og] - rmean[og] * iv;
    }

    const int g  = lane >> 2;
    const int l3 = lane & 3;
    const int wm = (warp >> 2) * 64;
    const int wn = (warp & 3) * 32;

    // cp.async source/dst for this thread (4 chunks of 16B per K-chunk)
    const uint32_t bs0 = smem_u32(&Bs[0][0][0]);
    const int brow = tid >> 5;           // via idx = tid + l*256: row = idx>>5
    // (recomputed per l below)

    // issue B chunk cc into buffer buf
    #define ISSUE_B(cc, buf) do {                                                  \
        const float* _src = xb + (size_t)((cc) * 32) * HW + pp0;                   \
        _Pragma("unroll")                                                          \
        for (int l = 0; l < 4; l++) {                                              \
            int idx = tid + l * 256;                                               \
            int r = idx >> 5, c16 = idx & 31;                                      \
            uint32_t d = bs0 + (buf) * (32*132*4) + r * 528 + c16 * 16;            \
            CP_ASYNC16(d, _src + (size_t)r * HW + c16 * 4);                        \
        }                                                                          \
        CP_COMMIT();                                                               \
    } while (0)

    float acc[4][4][4];
#pragma unroll
    for (int mi = 0; mi < 4; mi++)
#pragma unroll
        for (int ni = 0; ni < 4; ni++)
#pragma unroll
            for (int r = 0; r < 4; r++) acc[mi][ni][r] = 0.f;

    ISSUE_B(0, 0);

#pragma unroll 1
    for (int c = 0; c < 8; c++) {
        const int bufo = c & 1;
        // A staging LDG (L2-hot) — issue early
        float4 ra[4];
#pragma unroll
        for (int l = 0; l < 4; l++) {
            int idx = tid + l * 256;
            int oo = idx >> 3, kq = idx & 7;
            ra[l] = *reinterpret_cast<const float4*>(&w[(o0 + oo) * Cc + c * 32 + kq * 4]);
        }
        CP_WAIT0();          // B_c landed (this thread's view)
        __syncthreads();     // all warps done with bufs of iter c-1; B_c visible CTA-wide
        if (c + 1 < 8) ISSUE_B(c + 1, bufo ^ 1);
        // convert + STS A_c
#pragma unroll
        for (int l = 0; l < 4; l++) {
            int idx = tid + l * 256;
            int oo = idx >> 3, kq = idx & 7;
            __half2 hp[2] = { __floats2half2_rn(ra[l].x, ra[l].y),
                              __floats2half2_rn(ra[l].z, ra[l].w) };
            *reinterpret_cast<uint2*>(&As[bufo][oo][kq * 4]) = *reinterpret_cast<uint2*>(hp);
        }
        __syncthreads();     // A_c visible

#pragma unroll
        for (int s = 0; s < 2; s++) {
            const int k = s * 16 + 2 * l3;
            uint32_t a[4][4], bf[4][2];
#pragma unroll
            for (int mi = 0; mi < 4; mi++) {
                int m = wm + mi * 16 + g;
                a[mi][0] = *reinterpret_cast<const uint32_t*>(&As[bufo][m][k]);
                a[mi][1] = *reinterpret_cast<const uint32_t*>(&As[bufo][m + 8][k]);
                a[mi][2] = *reinterpret_cast<const uint32_t*>(&As[bufo][m][k + 8]);
                a[mi][3] = *reinterpret_cast<const uint32_t*>(&As[bufo][m + 8][k + 8]);
            }
#pragma unroll
            for (int ni = 0; ni < 4; ni++) {
                int p = wn + ni * 8 + g;
                __half2 h0 = __floats2half2_rn(Bs[bufo][k][p],     Bs[bufo][k + 1][p]);
                __half2 h1 = __floats2half2_rn(Bs[bufo][k + 8][p], Bs[bufo][k + 9][p]);
                bf[ni][0] = *reinterpret_cast<uint32_t*>(&h0);
                bf[ni][1] = *reinterpret_cast<uint32_t*>(&h1);
            }
#pragma unroll
            for (int mi = 0; mi < 4; mi++)
#pragma unroll
                for (int ni = 0; ni < 4; ni++)
                    mma_f16(acc[mi][ni], a[mi], bf[ni]);
        }
    }
    #undef ISSUE_B

    // epilogue: BN + ReLU + scatter into fp16 attn fragment layouts (identical to R10)
    int winv[4][2], nn[4][2];
#pragma unroll
    for (int ni = 0; ni < 4; ni++)
#pragma unroll
        for (int e = 0; e < 2; e++) {
            int pin = pp0 + wn + ni * 8 + 2 * l3 + e;
            int row = pin / 192;
            int col = pin - row * 192;
            winv[ni][e] = b * 576 + (row >> 3) * 24 + (col >> 3);
            nn[ni][e]   = ((row & 7) << 3) + (col & 7);
        }
#pragma unroll
    for (int mi = 0; mi < 4; mi++) {
#pragma unroll
        for (int rh = 0; rh < 2; rh++) {
            int ol = wm + mi * 16 + g + rh * 8;
            int o  = o0 + ol;
            float iv = sinv[ol], bz = sbz[ol];
            int qkv  = o >> 8;
            int head = (o >> 4) & 15;
            int d    = o & 15;
            int dl = (d >> 1) & 3, de = d & 1, dh = d >> 3;
            __half* gb = g_scratch + (size_t)qkv * QKV_STRIDE + head * 1024;
#pragma unroll
            for (int ni = 0; ni < 4; ni++)
#pragma unroll
                for (int e = 0; e < 2; e++) {
                    float t = acc[mi][ni][rh * 2 + e] * iv + bz;
                    t = t > 0.f ? t : 0.f;
                    int n = nn[ni][e];
                    int off;
                    if (qkv == 0) {
                        t *= 0.36067376f;   // 0.25 * log2(e) folded into q
                        off = (n >> 4) * 256 + ((((n & 7) << 2) | dl) << 3)
                            + (((n >> 3) & 1) << 1) + de + (dh << 2);
                    } else {
                        off = (n >> 3) * 128 + ((((n & 7) << 2) | dl) << 2)
                            + de + (dh << 1);
                    }
                    gb[(size_t)winv[ni][e] * 16384 + off] = __float2half_rn(t);
                }
        }
    }
}

// ---------------- attention: unchanged from R10 -----------------------------------------
__global__ __launch_bounds__(256, 4) void attn_kernel(
    const float* __restrict__ rel_table,
    float* __restrict__ out_attn, float* __restrict__ out_avg)
{
    __shared__ float biasl[232];

    const int tid  = threadIdx.x;
    const int w    = tid >> 5;
    const int lane = tid & 31;
    const int head = blockIdx.x & 15;
    const int wp   = blockIdx.x >> 4;

    if (tid < 225) biasl[tid] = rel_table[tid * 16 + head] * 1.4426950408f;
    __syncthreads();

    const int win   = wp * 2 + (w >> 2);
    const int slice = w & 3;
    const __half* qb = g_scratch + (size_t)(win * 16 + head) * 1024;
    const __half* kb = qb + QKV_STRIDE;

    uint4 av = *reinterpret_cast<const uint4*>(qb + slice * 256 + lane * 8);
    uint32_t a[4] = {av.x, av.y, av.z, av.w};

    float acc[8][4];
#pragma unroll
    for (int ni = 0; ni < 8; ni++) {
#pragma unroll
        for (int r = 0; r < 4; r++) acc[ni][r] = 0.f;
        uint2 bv = *reinterpret_cast<const uint2*>(kb + ni * 128 + lane * 4);
        uint32_t bf[2] = {bv.x, bv.y};
        mma_f16(acc[ni], a, bf);
    }

    const int g  = lane >> 2;
    const int l3 = lane & 3;
    const int X0 = g - 2 * l3 + 7;
#pragma unroll
    for (int ni = 0; ni < 8; ni++) {
        const float* r0 = &biasl[(slice * 2 - ni + 7) * 15];
        acc[ni][0] += r0[X0];
        acc[ni][1] += r0[X0 - 1];
        acc[ni][2] += r0[15 + X0];
        acc[ni][3] += r0[15 + X0 - 1];
    }

#pragma unroll
    for (int ni = 0; ni < 8; ni++)
#pragma unroll
        for (int e = 0; e < 2; e++) {
            float s = acc[ni][e] + acc[ni][2 + e];
            s += __shfl_xor_sync(0xffffffffu, s, 4);
            s += __shfl_xor_sync(0xffffffffu, s, 8);
            s += __shfl_xor_sync(0xffffffffu, s, 16);
            if (g == 0)
                atomicAdd(&out_avg[win * 64 + ni * 8 + 2 * l3 + e],
                          s * 6.7690154e-4f);   // ln2/1024
        }

#pragma unroll
    for (int h = 0; h < 2; h++) {
        float mx = fmaxf(acc[0][2*h], acc[0][2*h+1]);
#pragma unroll
        for (int ni = 1; ni < 8; ni++)
            mx = fmaxf(mx, fmaxf(acc[ni][2*h], acc[ni][2*h+1]));
        mx = fmaxf(mx, __shfl_xor_sync(0xffffffffu, mx, 1));
        mx = fmaxf(mx, __shfl_xor_sync(0xffffffffu, mx, 2));
        float sum = 0.f;
#pragma unroll
        for (int ni = 0; ni < 8; ni++) {
            acc[ni][2*h]   = ex2f(acc[ni][2*h]   - mx);
            acc[ni][2*h+1] = ex2f(acc[ni][2*h+1] - mx);
            sum += acc[ni][2*h] + acc[ni][2*h+1];
        }
        sum += __shfl_xor_sync(0xffffffffu, sum, 1);
        sum += __shfl_xor_sync(0xffffffffu, sum, 2);
        float rinv = __frcp_rn(sum);
#pragma unroll
        for (int ni = 0; ni < 8; ni++) {
            acc[ni][2*h]   *= rinv;
            acc[ni][2*h+1] *= rinv;
        }
    }

    float* ob = out_attn + ((size_t)(win * 16 + head) * 64 + slice * 16 + g) * 64 + 2 * l3;
#pragma unroll
    for (int ni = 0; ni < 8; ni++) {
        *reinterpret_cast<float2*>(ob + ni * 8)          = make_float2(acc[ni][0], acc[ni][1]);
        *reinterpret_cast<float2*>(ob + 8 * 64 + ni * 8) = make_float2(acc[ni][2], acc[ni][3]);
    }
}

extern "C" void kernel_launch(void* const* d_in, const int* in_sizes, int n_in,
                              void* d_out, int out_size) {
    const float* x     = (const float*)d_in[0];
    const float* w     = (const float*)d_in[1];
    const float* gamma = (const float*)d_in[2];
    const float* beta  = (const float*)d_in[3];
    const float* rmean = (const float*)d_in[4];
    const float* rvar  = (const float*)d_in[5];
    const float* rel   = (const float*)d_in[6];
    float* out     = (float*)d_out;
    float* out_avg = out + ATTN_ELEMS;

    static bool attr_set = false;
    if (!attr_set) {
        cudaFuncSetAttribute(proj_kernel, cudaFuncAttributeMaxDynamicSharedMemorySize,
                             PROJ_SMEM);
        attr_set = true;
    }
    cudaMemsetAsync(out_avg, 0, AVG_ELEMS * sizeof(float));
    proj_kernel<<<dim3(4, 576), 256, PROJ_SMEM>>>(x, w, gamma, beta, rmean, rvar);
    attn_kernel<<<9216, 256>>>(rel, out, out_avg);
}